// round 10
// baseline (speedup 1.0000x reference)
#include <cuda_runtime.h>
#include <cuda_bf16.h>
#include <stdint.h>

// ============================================================================
// VoxMLP: (1) trilinear gather of (g, grad g) with on-the-fly central diffs
//         (2) persistent FP8 (e4m3) mma.sync MLP, 512 thr, 32x32 warp tiles,
//             k-interleaved fp8 SMEM layout (all fragment loads = LDS.64),
//             fused output projection + Rodrigues rotation
// Output layout (float32): [0,B) = c0 ; [B,4B) = grad (B,3) ; [4B,7B) = rot
// ============================================================================

#define GD   256
#define SX   65536   // 256*256
#define SY   256

// ---------------------------------------------------------------------------
// Kernel 1: gather + gradient (known-good, ~104us)
// ---------------------------------------------------------------------------
__global__ void __launch_bounds__(256) gather_kernel(
    const float* __restrict__ x, const float* __restrict__ grid,
    float* __restrict__ out, int B)
{
    int p = blockIdx.x * blockDim.x + threadIdx.x;
    if (p >= B) return;

    float px = x[3*p+0], py = x[3*p+1], pz = x[3*p+2];
    float fx = (px + 1.0f) * 127.5f;
    float fy = (py + 1.0f) * 127.5f;
    float fz = (pz + 1.0f) * 127.5f;
    float x0f = floorf(fx), y0f = floorf(fy), z0f = floorf(fz);
    float xd = fx - x0f, yd = fy - y0f, zd = fz - z0f;

    int ix0 = min(max((int)x0f, 0), GD-1);
    int ix1 = min(max((int)x0f + 1, 0), GD-1);
    int iy0 = min(max((int)y0f, 0), GD-1);
    int iy1 = min(max((int)y0f + 1, 0), GD-1);
    int iz0 = min(max((int)z0f, 0), GD-1);
    int iz1 = min(max((int)z0f + 1, 0), GD-1);

    int pvx = max(ix0-1, 0), nxx = min(ix1+1, GD-1);
    int pvy = max(iy0-1, 0), nxy = min(iy1+1, GD-1);
    int pvz = max(iz0-1, 0), nxz = min(iz1+1, GD-1);

    int bx0 = ix0*SX, bx1 = ix1*SX;
    int by0 = iy0*SY, by1 = iy1*SY;
    int bpx = pvx*SX, bnx = nxx*SX;
    int bpy = pvy*SY, bny = nxy*SY;

    float v000 = __ldg(grid + bx0 + by0 + iz0);
    float v001 = __ldg(grid + bx0 + by0 + iz1);
    float v010 = __ldg(grid + bx0 + by1 + iz0);
    float v011 = __ldg(grid + bx0 + by1 + iz1);
    float v100 = __ldg(grid + bx1 + by0 + iz0);
    float v101 = __ldg(grid + bx1 + by0 + iz1);
    float v110 = __ldg(grid + bx1 + by1 + iz0);
    float v111 = __ldg(grid + bx1 + by1 + iz1);

    float xm00 = __ldg(grid + bpx + by0 + iz0);
    float xm01 = __ldg(grid + bpx + by0 + iz1);
    float xm10 = __ldg(grid + bpx + by1 + iz0);
    float xm11 = __ldg(grid + bpx + by1 + iz1);
    float xp00 = __ldg(grid + bnx + by0 + iz0);
    float xp01 = __ldg(grid + bnx + by0 + iz1);
    float xp10 = __ldg(grid + bnx + by1 + iz0);
    float xp11 = __ldg(grid + bnx + by1 + iz1);

    float ym00 = __ldg(grid + bx0 + bpy + iz0);
    float ym01 = __ldg(grid + bx0 + bpy + iz1);
    float ym10 = __ldg(grid + bx1 + bpy + iz0);
    float ym11 = __ldg(grid + bx1 + bpy + iz1);
    float yp00 = __ldg(grid + bx0 + bny + iz0);
    float yp01 = __ldg(grid + bx0 + bny + iz1);
    float yp10 = __ldg(grid + bx1 + bny + iz0);
    float yp11 = __ldg(grid + bx1 + bny + iz1);

    float zm00 = __ldg(grid + bx0 + by0 + pvz);
    float zm01 = __ldg(grid + bx0 + by1 + pvz);
    float zm10 = __ldg(grid + bx1 + by0 + pvz);
    float zm11 = __ldg(grid + bx1 + by1 + pvz);
    float zp00 = __ldg(grid + bx0 + by0 + nxz);
    float zp01 = __ldg(grid + bx0 + by1 + nxz);
    float zp10 = __ldg(grid + bx1 + by0 + nxz);
    float zp11 = __ldg(grid + bx1 + by1 + nxz);

    const float i2 = 63.75f;   // 1/(2*NDELTA)

    float dx000 = (v100 - xm00)*i2, dx001 = (v101 - xm01)*i2;
    float dx010 = (v110 - xm10)*i2, dx011 = (v111 - xm11)*i2;
    float dx100 = (xp00 - v000)*i2, dx101 = (xp01 - v001)*i2;
    float dx110 = (xp10 - v010)*i2, dx111 = (xp11 - v011)*i2;

    float dy000 = (v010 - ym00)*i2, dy001 = (v011 - ym01)*i2;
    float dy100 = (v110 - ym10)*i2, dy101 = (v111 - ym11)*i2;
    float dy010 = (yp00 - v000)*i2, dy011 = (yp01 - v001)*i2;
    float dy110 = (yp10 - v100)*i2, dy111 = (yp11 - v101)*i2;

    float dz000 = (v001 - zm00)*i2, dz010 = (v011 - zm01)*i2;
    float dz100 = (v101 - zm10)*i2, dz110 = (v111 - zm11)*i2;
    float dz001 = (zp00 - v000)*i2, dz011 = (zp01 - v010)*i2;
    float dz101 = (zp10 - v100)*i2, dz111 = (zp11 - v110)*i2;

    float xw0 = 1.0f - xd, yw0 = 1.0f - yd, zw0 = 1.0f - zd;
    float w000 = xw0*yw0*zw0, w001 = xw0*yw0*zd;
    float w010 = xw0*yd *zw0, w011 = xw0*yd *zd;
    float w100 = xd *yw0*zw0, w101 = xd *yw0*zd;
    float w110 = xd *yd *zw0, w111 = xd *yd *zd;

    float c0 = w000*v000 + w001*v001 + w010*v010 + w011*v011
             + w100*v100 + w101*v101 + w110*v110 + w111*v111;
    float gx = w000*dx000 + w001*dx001 + w010*dx010 + w011*dx011
             + w100*dx100 + w101*dx101 + w110*dx110 + w111*dx111;
    float gy = w000*dy000 + w001*dy001 + w010*dy010 + w011*dy011
             + w100*dy100 + w101*dy101 + w110*dy110 + w111*dy111;
    float gz = w000*dz000 + w001*dz001 + w010*dz010 + w011*dz011
             + w100*dz100 + w101*dz101 + w110*dz110 + w111*dz111;

    out[p]         = c0;
    out[B + 3*p+0] = gx;
    out[B + 3*p+1] = gy;
    out[B + 3*p+2] = gz;
}

// ---------------------------------------------------------------------------
// Kernel 2: FP8 MLP (512 threads; warp w: rg = w&3 -> rows 32rg..+31,
//           ch = w>>2 -> cols 32ch..+31; named barrier rg+1 over 128 thr)
// fp8 layout: per row, k bytes interleaved so (k, k+16) are adjacent:
//   il(k) = (k&~31) + 8*((k>>2)&3) + 4*((k>>4)&1) + (k&3)
// pitch 160 (W3: 288): pitch/4 mod 32 == 8 -> conflict-free LDS.64
// ---------------------------------------------------------------------------
#define PA   160
#define PW3  288
#define OFF_W0   0        // 128 x 160  (k 0..63, k63 = 0)
#define OFF_W1   20480
#define OFF_W2   40960
#define OFF_W3   61440    // 128 x 288  (k 0..191, k191 = 0)
#define OFF_HA   98304
#define OFF_HB   118784
#define OFF_FEAT 139264   // k 0..63, k63 = 0
#define OFF_BIAS 159744   // 4 x 128 f32
#define OFF_WO   161792   // 128 x 3 f32
#define OFF_BO   163328   // 3 f32
#define OFF_RED  163344   // 4 ch x 128 rows x 3 f32
#define SMEM_BYTES 169488

__device__ __forceinline__ int ilk(int k) {
    return (k & ~31) + (((k >> 2) & 3) << 3) + (((k >> 4) & 1) << 2) + (k & 3);
}
__device__ __forceinline__ uint16_t f2e4m3x2(float hi, float lo) {
    uint16_t v;
    asm("cvt.rn.satfinite.e4m3x2.f32 %0, %1, %2;" : "=h"(v) : "f"(hi), "f"(lo));
    return v;
}
__device__ __forceinline__ void lds64(uint32_t& x, uint32_t& y, uint32_t a) {
    asm volatile("ld.shared.v2.u32 {%0,%1}, [%2];" : "=r"(x), "=r"(y) : "r"(a));
}
__device__ __forceinline__ void qmma(float* c,
    uint32_t a0, uint32_t a1, uint32_t a2, uint32_t a3,
    uint32_t b0, uint32_t b1)
{
    asm("mma.sync.aligned.m16n8k32.row.col.f32.e4m3.e4m3.f32 "
        "{%0,%1,%2,%3}, {%4,%5,%6,%7}, {%8,%9}, {%0,%1,%2,%3};"
        : "+f"(c[0]), "+f"(c[1]), "+f"(c[2]), "+f"(c[3])
        : "r"(a0), "r"(a1), "r"(a2), "r"(a3), "r"(b0), "r"(b1));
}

// 32x32 warp tile over `nchunks` k32 chunks, double-buffered LDS.64 frags.
__device__ __forceinline__ void gemm_fp8(uint32_t smb, int aOff, int aPitch,
    int wOff, int wPitch, int nchunks, float (&acc)[2][4][4], int lane,
    int m0, int ncol0)
{
    const int r8 = lane >> 2, q = lane & 3;
    uint32_t aA = smb + (uint32_t)aOff + (uint32_t)(m0 + r8) * aPitch + 8*q;
    uint32_t bA = smb + (uint32_t)wOff + (uint32_t)(ncol0 + r8) * wPitch + 8*q;

    uint32_t A[2][2][4], Bf[2][4][2];
    lds64(A[0][0][0], A[0][0][2], aA);
    lds64(A[0][0][1], A[0][0][3], aA + 8u*aPitch);
    lds64(A[0][1][0], A[0][1][2], aA + 16u*aPitch);
    lds64(A[0][1][1], A[0][1][3], aA + 24u*aPitch);
    lds64(Bf[0][0][0], Bf[0][0][1], bA);
    lds64(Bf[0][1][0], Bf[0][1][1], bA + 8u*wPitch);
    lds64(Bf[0][2][0], Bf[0][2][1], bA + 16u*wPitch);
    lds64(Bf[0][3][0], Bf[0][3][1], bA + 24u*wPitch);

    #pragma unroll
    for (int c = 0; c < nchunks; c++) {
        const int cur = c & 1, nxt = cur ^ 1;
        if (c + 1 < nchunks) {
            aA += 32; bA += 32;
            lds64(A[nxt][0][0], A[nxt][0][2], aA);
            lds64(A[nxt][0][1], A[nxt][0][3], aA + 8u*aPitch);
            lds64(A[nxt][1][0], A[nxt][1][2], aA + 16u*aPitch);
            lds64(A[nxt][1][1], A[nxt][1][3], aA + 24u*aPitch);
            lds64(Bf[nxt][0][0], Bf[nxt][0][1], bA);
            lds64(Bf[nxt][1][0], Bf[nxt][1][1], bA + 8u*wPitch);
            lds64(Bf[nxt][2][0], Bf[nxt][2][1], bA + 16u*wPitch);
            lds64(Bf[nxt][3][0], Bf[nxt][3][1], bA + 24u*wPitch);
        }
        #pragma unroll
        for (int mt = 0; mt < 2; mt++)
            #pragma unroll
            for (int nt = 0; nt < 4; nt++)
                qmma(acc[mt][nt], A[cur][mt][0], A[cur][mt][1],
                     A[cur][mt][2], A[cur][mt][3],
                     Bf[cur][nt][0], Bf[cur][nt][1]);
    }
}

// bias + relu -> fp8 interleaved store
__device__ __forceinline__ void epi_fp8(uint32_t smb, int outOff,
    const float* bias, float (&acc)[2][4][4], int lane, int m0, int ncol0)
{
    const int r8 = lane >> 2, q = lane & 3;
    #pragma unroll
    for (int mt = 0; mt < 2; mt++) {
        int r = m0 + 16*mt + r8;
        #pragma unroll
        for (int nt = 0; nt < 4; nt++) {
            int n = ncol0 + 8*nt + 2*q;
            float b0v = bias[n], b1v = bias[n+1];
            float v00 = fmaxf(acc[mt][nt][0] + b0v, 0.f);
            float v01 = fmaxf(acc[mt][nt][1] + b1v, 0.f);
            float v10 = fmaxf(acc[mt][nt][2] + b0v, 0.f);
            float v11 = fmaxf(acc[mt][nt][3] + b1v, 0.f);
            uint16_t p0 = f2e4m3x2(v01, v00);
            uint16_t p1 = f2e4m3x2(v11, v10);
            uint32_t base = smb + (uint32_t)outOff + (uint32_t)ilk(n);
            asm volatile("st.shared.u16 [%0], %1;"
                         :: "r"(base + (uint32_t)r*PA), "h"(p0) : "memory");
            asm volatile("st.shared.u16 [%0], %1;"
                         :: "r"(base + (uint32_t)(r+8)*PA), "h"(p1) : "memory");
        }
    }
}

__device__ __forceinline__ void zero_acc(float (&acc)[2][4][4]) {
    #pragma unroll
    for (int h = 0; h < 2; h++)
        #pragma unroll
        for (int i = 0; i < 4; i++)
            #pragma unroll
            for (int j = 0; j < 4; j++) acc[h][i][j] = 0.f;
}

__global__ void __launch_bounds__(512, 1) mlp_kernel(
    const float* __restrict__ x,
    const float* __restrict__ w0, const float* __restrict__ b0,
    const float* __restrict__ w1, const float* __restrict__ b1,
    const float* __restrict__ w2, const float* __restrict__ b2,
    const float* __restrict__ w3, const float* __restrict__ b3,
    const float* __restrict__ wo, const float* __restrict__ bo,
    float* __restrict__ out, int B)
{
    extern __shared__ char sm[];
    const int t = threadIdx.x;
    const uint32_t smb = [&]{ uint32_t a;
        asm("{ .reg .u64 t; cvta.to.shared.u64 t, %1; cvt.u32.u64 %0, t; }"
            : "=r"(a) : "l"(sm)); return a; }();

    // ---- weights -> fp8 interleaved SMEM ----
    for (int i = t; i < 128*64; i += 512) {           // W0 (k 0..63)
        int n = i >> 6, k = i & 63;
        float v = (k < 63) ? w0[k*128 + n] : 0.f;
        sm[OFF_W0 + n*PA + ilk(k)] = (char)(uint8_t)f2e4m3x2(0.f, v);
    }
    for (int i = t; i < 128*128; i += 512) {          // W1, W2
        int n = i >> 7, k = i & 127;
        sm[OFF_W1 + n*PA + ilk(k)] = (char)(uint8_t)f2e4m3x2(0.f, w1[k*128 + n]);
        sm[OFF_W2 + n*PA + ilk(k)] = (char)(uint8_t)f2e4m3x2(0.f, w2[k*128 + n]);
    }
    for (int i = t; i < 128*192; i += 512) {          // W3 (k 0..191)
        int n = i / 192, k = i % 192;
        float v = (k < 191) ? w3[k*128 + n] : 0.f;
        sm[OFF_W3 + n*PW3 + ilk(k)] = (char)(uint8_t)f2e4m3x2(0.f, v);
    }
    if (t < 128) {
        float* bb = (float*)(sm + OFF_BIAS);
        bb[t] = b0[t]; bb[128 + t] = b1[t]; bb[256 + t] = b2[t]; bb[384 + t] = b3[t];
        float* wos = (float*)(sm + OFF_WO);
        wos[3*t+0] = wo[3*t+0]; wos[3*t+1] = wo[3*t+1]; wos[3*t+2] = wo[3*t+2];
    }
    if (t < 3) ((float*)(sm + OFF_BO))[t] = bo[t];
    __syncthreads();

    const int lane = t & 31, warp = t >> 5;
    const int rg = warp & 3, ch = warp >> 2;   // rg = SMSP
    const int m0 = 32 * rg, ncol0 = 32 * ch;
    const int barid = rg + 1;
    const int r8 = lane >> 2, q = lane & 3;
    const int ntiles = (B + 127) / 128;
    const float* bias = (const float*)(sm + OFF_BIAS);
    const float* wos  = (const float*)(sm + OFF_WO);
    const float* bos  = (const float*)(sm + OFF_BO);
    float* red = (float*)(sm + OFF_RED);

    for (int tile = blockIdx.x; tile < ntiles; tile += gridDim.x) {
        int pbase = tile * 128;

        // ---- positional encoding -> FEAT (ch==0 warps; row = m0+lane) ----
        if (ch == 0) {
            int row = m0 + lane;
            int p = pbase + row;
            float f[64];
            float xv0 = 0.f, xv1 = 0.f, xv2 = 0.f;
            if (p < B) { xv0 = x[3*p]; xv1 = x[3*p+1]; xv2 = x[3*p+2]; }
            f[0] = xv0; f[1] = xv1; f[2] = xv2; f[63] = 0.f;
            float s0 = sinf(xv0), c0v = cosf(xv0);
            float s1 = sinf(xv1), c1v = cosf(xv1);
            float s2 = sinf(xv2), c2v = cosf(xv2);
            #pragma unroll
            for (int b = 0; b < 10; b++) {
                int fo = 3 + b*6;
                f[fo+0] = s0; f[fo+1] = s1; f[fo+2] = s2;
                f[fo+3] = c0v; f[fo+4] = c1v; f[fo+5] = c2v;
                float ns0 = 2.f*s0*c0v, nc0 = 2.f*c0v*c0v - 1.f;
                float ns1 = 2.f*s1*c1v, nc1 = 2.f*c1v*c1v - 1.f;
                float ns2 = 2.f*s2*c2v, nc2 = 2.f*c2v*c2v - 1.f;
                s0 = ns0; c0v = nc0; s1 = ns1; c1v = nc1; s2 = ns2; c2v = nc2;
            }
            uint32_t rowA = smb + OFF_FEAT + (uint32_t)row * PA;
            #pragma unroll
            for (int c = 0; c < 2; c++)
                #pragma unroll
                for (int qq = 0; qq < 4; qq++) {
                    int k0 = 32*c + 4*qq;
                    uint32_t wlo = (uint32_t)f2e4m3x2(f[k0+1], f[k0+0])
                                 | ((uint32_t)f2e4m3x2(f[k0+3], f[k0+2]) << 16);
                    uint32_t whi = (uint32_t)f2e4m3x2(f[k0+17], f[k0+16])
                                 | ((uint32_t)f2e4m3x2(f[k0+19], f[k0+18]) << 16);
                    asm volatile("st.shared.v2.u32 [%0], {%1,%2};"
                                 :: "r"(rowA + 32*c + 8*qq), "r"(wlo), "r"(whi)
                                 : "memory");
                }
        }
        asm volatile("bar.sync %0, 128;" :: "r"(barid) : "memory");

        float acc[2][4][4];

        // L0: FEAT (k64) -> HA
        zero_acc(acc);
        gemm_fp8(smb, OFF_FEAT, PA, OFF_W0, PA, 2, acc, lane, m0, ncol0);
        epi_fp8(smb, OFF_HA, bias + 0, acc, lane, m0, ncol0);
        asm volatile("bar.sync %0, 128;" :: "r"(barid) : "memory");

        // L1: HA -> HB
        zero_acc(acc);
        gemm_fp8(smb, OFF_HA, PA, OFF_W1, PA, 4, acc, lane, m0, ncol0);
        epi_fp8(smb, OFF_HB, bias + 128, acc, lane, m0, ncol0);
        asm volatile("bar.sync %0, 128;" :: "r"(barid) : "memory");

        // L2: HB -> HA
        zero_acc(acc);
        gemm_fp8(smb, OFF_HB, PA, OFF_W2, PA, 4, acc, lane, m0, ncol0);
        epi_fp8(smb, OFF_HA, bias + 256, acc, lane, m0, ncol0);
        asm volatile("bar.sync %0, 128;" :: "r"(barid) : "memory");

        // L3: concat[HA (k 0..127), FEAT (k 128..191)] -> projection partials
        zero_acc(acc);
        gemm_fp8(smb, OFF_HA, PA, OFF_W3, PW3, 4, acc, lane, m0, ncol0);
        gemm_fp8(smb, OFF_FEAT, PA, OFF_W3 + 128, PW3, 2, acc, lane, m0, ncol0);
        {
            float s[4][3];
            #pragma unroll
            for (int i = 0; i < 4; i++) { s[i][0] = s[i][1] = s[i][2] = 0.f; }
            const float* b3s = bias + 384;
            #pragma unroll
            for (int mt = 0; mt < 2; mt++) {
                #pragma unroll
                for (int nt = 0; nt < 4; nt++) {
                    int n = ncol0 + 8*nt + 2*q;
                    float b0v = b3s[n], b1v = b3s[n+1];
                    float v00 = fmaxf(acc[mt][nt][0] + b0v, 0.f);
                    float v01 = fmaxf(acc[mt][nt][1] + b1v, 0.f);
                    float v10 = fmaxf(acc[mt][nt][2] + b0v, 0.f);
                    float v11 = fmaxf(acc[mt][nt][3] + b1v, 0.f);
                    const float* wp = wos + 3*n;   // cols n, n+1: 6 floats
                    float w00 = wp[0], w01 = wp[1], w02 = wp[2];
                    float w10 = wp[3], w11 = wp[4], w12 = wp[5];
                    s[2*mt+0][0] += v00*w00 + v01*w10;
                    s[2*mt+0][1] += v00*w01 + v01*w11;
                    s[2*mt+0][2] += v00*w02 + v01*w12;
                    s[2*mt+1][0] += v10*w00 + v11*w10;
                    s[2*mt+1][1] += v10*w01 + v11*w11;
                    s[2*mt+1][2] += v10*w02 + v11*w12;
                }
            }
            #pragma unroll
            for (int i = 0; i < 4; i++)
                #pragma unroll
                for (int j = 0; j < 3; j++) {
                    s[i][j] += __shfl_xor_sync(0xffffffff, s[i][j], 1);
                    s[i][j] += __shfl_xor_sync(0xffffffff, s[i][j], 2);
                }
            if (q == 0) {
                #pragma unroll
                for (int i = 0; i < 4; i++) {
                    int row = m0 + 16*(i >> 1) + 8*(i & 1) + r8;
                    float* rp = red + (ch*128 + row)*3;
                    rp[0] = s[i][0]; rp[1] = s[i][1]; rp[2] = s[i][2];
                }
            }
        }
        asm volatile("bar.sync %0, 128;" :: "r"(barid) : "memory");

        // ---- Rodrigues (lanes 0..7 of each warp; row = m0 + 8*ch + lane) ----
        if (lane < 8) {
            int row = m0 + 8*ch + lane;
            int p = pbase + row;
            if (p < B) {
                float r0 = bos[0], r1 = bos[1], r2 = bos[2];
                #pragma unroll
                for (int c = 0; c < 4; c++) {
                    const float* rp = red + (c*128 + row)*3;
                    r0 += rp[0]; r1 += rp[1]; r2 += rp[2];
                }
                float theta = sqrtf(r0*r0 + r1*r1 + r2*r2 + 1e-12f);
                float it = 1.f / theta;
                float e0 = r0*it, e1 = r1*it, e2 = r2*it;
                float cd0 = out[B + 3*p], cd1 = out[B + 3*p+1], cd2 = out[B + 3*p+2];
                float a = sqrtf(cd0*cd0 + cd1*cd1 + cd2*cd2 + 1e-12f);
                float ia = 1.f / a;
                float v0 = cd0*ia, v1 = cd1*ia, v2 = cd2*ia;
                float ct = cosf(theta), st = sinf(theta);
                float cr0 = e1*v2 - e2*v1;
                float cr1 = e2*v0 - e0*v2;
                float cr2 = e0*v1 - e1*v0;
                float dt = e0*v0 + e1*v1 + e2*v2;
                float omc = (1.f - ct) * dt;
                out[4*B + 3*p+0] = a * (ct*v0 + st*cr0 + omc*e0);
                out[4*B + 3*p+1] = a * (ct*v1 + st*cr1 + omc*e1);
                out[4*B + 3*p+2] = a * (ct*v2 + st*cr2 + omc*e2);
            }
        }
        asm volatile("bar.sync %0, 128;" :: "r"(barid) : "memory");
    }
}

// ---------------------------------------------------------------------------
extern "C" void kernel_launch(void* const* d_in, const int* in_sizes, int n_in,
                              void* d_out, int out_size)
{
    const float* x    = (const float*)d_in[0];
    const float* grid = (const float*)d_in[1];
    const float* w0   = (const float*)d_in[2];
    const float* b0   = (const float*)d_in[3];
    const float* w1   = (const float*)d_in[4];
    const float* b1   = (const float*)d_in[5];
    const float* w2   = (const float*)d_in[6];
    const float* b2   = (const float*)d_in[7];
    const float* w3   = (const float*)d_in[8];
    const float* b3   = (const float*)d_in[9];
    const float* wo   = (const float*)d_in[10];
    const float* bo   = (const float*)d_in[11];
    float* out = (float*)d_out;
    int B = in_sizes[0] / 3;

    gather_kernel<<<(B + 255) / 256, 256>>>(x, grid, out, B);

    int nsm = 148;
    cudaDeviceGetAttribute(&nsm, cudaDevAttrMultiProcessorCount, 0);
    cudaFuncSetAttribute(mlp_kernel,
                         cudaFuncAttributeMaxDynamicSharedMemorySize, SMEM_BYTES);
    mlp_kernel<<<nsm, 512, SMEM_BYTES>>>(x, w0, b0, w1, b1, w2, b2,
                                         w3, b3, wo, bo, out, B);
}

// round 11
// speedup vs baseline: 1.1488x; 1.1488x over previous
#include <cuda_runtime.h>
#include <cuda_bf16.h>
#include <stdint.h>

// ============================================================================
// VoxMLP: (1) trilinear gather of (g, grad g) with on-the-fly central diffs
//         (2) persistent bf16 mma.sync MLP: 16 warps = 4 independent groups,
//             each group = 4 warps spread over the 4 SMSPs, each owning its
//             own stream of 32-point tiles (de-phased pipes), fused output
//             projection + Rodrigues rotation
// Output layout (float32): [0,B) = c0 ; [B,4B) = grad (B,3) ; [4B,7B) = rot
// ============================================================================

#define GD   256
#define SX   65536   // 256*256
#define SY   256

// ---------------------------------------------------------------------------
// Kernel 1: gather + gradient (known-good, ~104us)
// ---------------------------------------------------------------------------
__global__ void __launch_bounds__(256) gather_kernel(
    const float* __restrict__ x, const float* __restrict__ grid,
    float* __restrict__ out, int B)
{
    int p = blockIdx.x * blockDim.x + threadIdx.x;
    if (p >= B) return;

    float px = x[3*p+0], py = x[3*p+1], pz = x[3*p+2];
    float fx = (px + 1.0f) * 127.5f;
    float fy = (py + 1.0f) * 127.5f;
    float fz = (pz + 1.0f) * 127.5f;
    float x0f = floorf(fx), y0f = floorf(fy), z0f = floorf(fz);
    float xd = fx - x0f, yd = fy - y0f, zd = fz - z0f;

    int ix0 = min(max((int)x0f, 0), GD-1);
    int ix1 = min(max((int)x0f + 1, 0), GD-1);
    int iy0 = min(max((int)y0f, 0), GD-1);
    int iy1 = min(max((int)y0f + 1, 0), GD-1);
    int iz0 = min(max((int)z0f, 0), GD-1);
    int iz1 = min(max((int)z0f + 1, 0), GD-1);

    int pvx = max(ix0-1, 0), nxx = min(ix1+1, GD-1);
    int pvy = max(iy0-1, 0), nxy = min(iy1+1, GD-1);
    int pvz = max(iz0-1, 0), nxz = min(iz1+1, GD-1);

    int bx0 = ix0*SX, bx1 = ix1*SX;
    int by0 = iy0*SY, by1 = iy1*SY;
    int bpx = pvx*SX, bnx = nxx*SX;
    int bpy = pvy*SY, bny = nxy*SY;

    float v000 = __ldg(grid + bx0 + by0 + iz0);
    float v001 = __ldg(grid + bx0 + by0 + iz1);
    float v010 = __ldg(grid + bx0 + by1 + iz0);
    float v011 = __ldg(grid + bx0 + by1 + iz1);
    float v100 = __ldg(grid + bx1 + by0 + iz0);
    float v101 = __ldg(grid + bx1 + by0 + iz1);
    float v110 = __ldg(grid + bx1 + by1 + iz0);
    float v111 = __ldg(grid + bx1 + by1 + iz1);

    float xm00 = __ldg(grid + bpx + by0 + iz0);
    float xm01 = __ldg(grid + bpx + by0 + iz1);
    float xm10 = __ldg(grid + bpx + by1 + iz0);
    float xm11 = __ldg(grid + bpx + by1 + iz1);
    float xp00 = __ldg(grid + bnx + by0 + iz0);
    float xp01 = __ldg(grid + bnx + by0 + iz1);
    float xp10 = __ldg(grid + bnx + by1 + iz0);
    float xp11 = __ldg(grid + bnx + by1 + iz1);

    float ym00 = __ldg(grid + bx0 + bpy + iz0);
    float ym01 = __ldg(grid + bx0 + bpy + iz1);
    float ym10 = __ldg(grid + bx1 + bpy + iz0);
    float ym11 = __ldg(grid + bx1 + bpy + iz1);
    float yp00 = __ldg(grid + bx0 + bny + iz0);
    float yp01 = __ldg(grid + bx0 + bny + iz1);
    float yp10 = __ldg(grid + bx1 + bny + iz0);
    float yp11 = __ldg(grid + bx1 + bny + iz1);

    float zm00 = __ldg(grid + bx0 + by0 + pvz);
    float zm01 = __ldg(grid + bx0 + by1 + pvz);
    float zm10 = __ldg(grid + bx1 + by0 + pvz);
    float zm11 = __ldg(grid + bx1 + by1 + pvz);
    float zp00 = __ldg(grid + bx0 + by0 + nxz);
    float zp01 = __ldg(grid + bx0 + by1 + nxz);
    float zp10 = __ldg(grid + bx1 + by0 + nxz);
    float zp11 = __ldg(grid + bx1 + by1 + nxz);

    const float i2 = 63.75f;   // 1/(2*NDELTA)

    float dx000 = (v100 - xm00)*i2, dx001 = (v101 - xm01)*i2;
    float dx010 = (v110 - xm10)*i2, dx011 = (v111 - xm11)*i2;
    float dx100 = (xp00 - v000)*i2, dx101 = (xp01 - v001)*i2;
    float dx110 = (xp10 - v010)*i2, dx111 = (xp11 - v011)*i2;

    float dy000 = (v010 - ym00)*i2, dy001 = (v011 - ym01)*i2;
    float dy100 = (v110 - ym10)*i2, dy101 = (v111 - ym11)*i2;
    float dy010 = (yp00 - v000)*i2, dy011 = (yp01 - v001)*i2;
    float dy110 = (yp10 - v100)*i2, dy111 = (yp11 - v101)*i2;

    float dz000 = (v001 - zm00)*i2, dz010 = (v011 - zm01)*i2;
    float dz100 = (v101 - zm10)*i2, dz110 = (v111 - zm11)*i2;
    float dz001 = (zp00 - v000)*i2, dz011 = (zp01 - v010)*i2;
    float dz101 = (zp10 - v100)*i2, dz111 = (zp11 - v110)*i2;

    float xw0 = 1.0f - xd, yw0 = 1.0f - yd, zw0 = 1.0f - zd;
    float w000 = xw0*yw0*zw0, w001 = xw0*yw0*zd;
    float w010 = xw0*yd *zw0, w011 = xw0*yd *zd;
    float w100 = xd *yw0*zw0, w101 = xd *yw0*zd;
    float w110 = xd *yd *zw0, w111 = xd *yd *zd;

    float c0 = w000*v000 + w001*v001 + w010*v010 + w011*v011
             + w100*v100 + w101*v101 + w110*v110 + w111*v111;
    float gx = w000*dx000 + w001*dx001 + w010*dx010 + w011*dx011
             + w100*dx100 + w101*dx101 + w110*dx110 + w111*dx111;
    float gy = w000*dy000 + w001*dy001 + w010*dy010 + w011*dy011
             + w100*dy100 + w101*dy101 + w110*dy110 + w111*dy111;
    float gz = w000*dz000 + w001*dz001 + w010*dz010 + w011*dz011
             + w100*dz100 + w101*dz101 + w110*dz110 + w111*dz111;

    out[p]         = c0;
    out[B + 3*p+0] = gx;
    out[B + 3*p+1] = gy;
    out[B + 3*p+2] = gz;
}

// ---------------------------------------------------------------------------
// Kernel 2: persistent bf16 MMA MLP + Rodrigues (512 threads)
// Warp w: group rg = w>>2 (smem rows 32rg..+31, OWN tile stream),
//         ch = w&3 (cols 32ch..+31). SMSP of w = w&3 -> group spread over
//         all 4 SMSPs. Named barrier (rg+1) over the group's 128 threads.
// Pitches: pitch/4 mod 32 == 4 -> conflict-free LDSM/LDS/STS.
// ---------------------------------------------------------------------------
#define PW0   144   // w0t: 128 rows x 72 bf16 (k=0..63, k63 zero pad)
#define PW1   272   // w1t/w2t: 128 x 136 bf16
#define PW3   400   // w3t: 128 x 200 bf16 (k=0..191, k191 zero)
#define PBA   400   // bufA: 128 rows x 200 bf16 (cols 128..191 = feats)
#define PBB   272   // bufB: 128 rows x 136 bf16
#define OFF_W0   0
#define OFF_W1   18432
#define OFF_W2   53248
#define OFF_W3   88064
#define OFF_BUFA 139264
#define OFF_BUFB 190464
#define OFF_BIAS 225280   // 4 x 128 f32
#define OFF_WO   227328   // 128 x 3 f32
#define OFF_BO   228864   // 3 f32
#define SMEM_BYTES 228880

__device__ __forceinline__ void ldsm4(uint32_t& r0, uint32_t& r1,
                                      uint32_t& r2, uint32_t& r3, uint32_t a)
{
    asm volatile("ldmatrix.sync.aligned.m8n8.x4.shared.b16 {%0,%1,%2,%3}, [%4];"
                 : "=r"(r0), "=r"(r1), "=r"(r2), "=r"(r3) : "r"(a));
}

__device__ __forceinline__ void mma16(float* c,
    uint32_t a0, uint32_t a1, uint32_t a2, uint32_t a3,
    uint32_t b0, uint32_t b1)
{
    asm("mma.sync.aligned.m16n8k16.row.col.f32.bf16.bf16.f32 "
        "{%0,%1,%2,%3}, {%4,%5,%6,%7}, {%8,%9}, {%0,%1,%2,%3};"
        : "+f"(c[0]), "+f"(c[1]), "+f"(c[2]), "+f"(c[3])
        : "r"(a0), "r"(a1), "r"(a2), "r"(a3), "r"(b0), "r"(b1));
}

// 32 rows x 32 cols GEMM chunk over `ksteps` k16 steps, double-buffered frags.
__device__ __forceinline__ void gemm32x32(uint32_t smb,
    int inOff, int inPitch, int wOff, int wPitch, int ksteps,
    float (&acc)[2][4][4], int lane, int m0, int ncol0)
{
    const int l7 = lane & 7, l8 = (lane >> 3) & 1, l16 = lane >> 4;
    uint32_t aA0 = smb + inOff + (uint32_t)(m0 + l7 + 8*l8) * inPitch + 16*l16;
    uint32_t aA1 = aA0 + 16u * inPitch;
    uint32_t bA  = smb + wOff + (uint32_t)(ncol0 + l7 + 8*l16) * wPitch + 16*l8;

    uint32_t a0[2][4], a1[2][4], bb[2][2][4];
    ldsm4(a0[0][0], a0[0][1], a0[0][2], a0[0][3], aA0);
    ldsm4(a1[0][0], a1[0][1], a1[0][2], a1[0][3], aA1);
    #pragma unroll
    for (int pr = 0; pr < 2; pr++)
        ldsm4(bb[0][pr][0], bb[0][pr][1], bb[0][pr][2], bb[0][pr][3],
              bA + (uint32_t)(pr * 16) * wPitch);

    #pragma unroll
    for (int kk = 0; kk < ksteps; kk++) {
        const int cur = kk & 1, nxt = cur ^ 1;
        if (kk + 1 < ksteps) {
            aA0 += 32; aA1 += 32; bA += 32;
            ldsm4(a0[nxt][0], a0[nxt][1], a0[nxt][2], a0[nxt][3], aA0);
            ldsm4(a1[nxt][0], a1[nxt][1], a1[nxt][2], a1[nxt][3], aA1);
            #pragma unroll
            for (int pr = 0; pr < 2; pr++)
                ldsm4(bb[nxt][pr][0], bb[nxt][pr][1], bb[nxt][pr][2], bb[nxt][pr][3],
                      bA + (uint32_t)(pr * 16) * wPitch);
        }
        #pragma unroll
        for (int pr = 0; pr < 2; pr++) {
            mma16(acc[0][2*pr+0], a0[cur][0], a0[cur][1], a0[cur][2], a0[cur][3],
                  bb[cur][pr][0], bb[cur][pr][1]);
            mma16(acc[1][2*pr+0], a1[cur][0], a1[cur][1], a1[cur][2], a1[cur][3],
                  bb[cur][pr][0], bb[cur][pr][1]);
            mma16(acc[0][2*pr+1], a0[cur][0], a0[cur][1], a0[cur][2], a0[cur][3],
                  bb[cur][pr][2], bb[cur][pr][3]);
            mma16(acc[1][2*pr+1], a1[cur][0], a1[cur][1], a1[cur][2], a1[cur][3],
                  bb[cur][pr][2], bb[cur][pr][3]);
        }
    }
}

__device__ __forceinline__ void epi32x32(char* sm, int outOff, int outPitch,
    const float* bias, float (&acc)[2][4][4], int lane, int m0, int ncol0)
{
    const int g = lane >> 2, q = lane & 3;
    #pragma unroll
    for (int h = 0; h < 2; h++) {
        char* o0 = sm + outOff + (m0 + 16*h + g) * outPitch + 2*ncol0 + 4*q;
        #pragma unroll
        for (int nt = 0; nt < 4; nt++) {
            int n = ncol0 + nt*8 + 2*q;
            float bv0 = bias[n], bv1 = bias[n+1];
            float c0 = fmaxf(acc[h][nt][0] + bv0, 0.f);
            float c1 = fmaxf(acc[h][nt][1] + bv1, 0.f);
            float c2 = fmaxf(acc[h][nt][2] + bv0, 0.f);
            float c3 = fmaxf(acc[h][nt][3] + bv1, 0.f);
            uint32_t p01, p23;
            asm("cvt.rn.bf16x2.f32 %0, %1, %2;" : "=r"(p01) : "f"(c1), "f"(c0));
            asm("cvt.rn.bf16x2.f32 %0, %1, %2;" : "=r"(p23) : "f"(c3), "f"(c2));
            *(uint32_t*)(o0 + nt*16)              = p01;
            *(uint32_t*)(o0 + 8*outPitch + nt*16) = p23;
        }
    }
}

__device__ __forceinline__ void zero_acc(float (&acc)[2][4][4]) {
    #pragma unroll
    for (int h = 0; h < 2; h++)
        #pragma unroll
        for (int i = 0; i < 4; i++)
            #pragma unroll
            for (int j = 0; j < 4; j++) acc[h][i][j] = 0.f;
}

__global__ void __launch_bounds__(512, 1) mlp_kernel(
    const float* __restrict__ x,
    const float* __restrict__ w0, const float* __restrict__ b0,
    const float* __restrict__ w1, const float* __restrict__ b1,
    const float* __restrict__ w2, const float* __restrict__ b2,
    const float* __restrict__ w3, const float* __restrict__ b3,
    const float* __restrict__ wo, const float* __restrict__ bo,
    float* __restrict__ out, int B)
{
    extern __shared__ char sm[];
    const int t = threadIdx.x;

    // ---- load + transpose weights into SMEM (bf16), biases/wo as f32 ----
    for (int i = t; i < 128*64; i += 512) {           // w0t
        int n = i >> 6, k = i & 63;
        ((__nv_bfloat16*)(sm + OFF_W0 + n*PW0))[k] =
            (k < 63) ? __float2bfloat16(w0[k*128 + n]) : __float2bfloat16(0.f);
    }
    for (int i = t; i < 128*128; i += 512) {          // w1t, w2t
        int n = i >> 7, k = i & 127;
        ((__nv_bfloat16*)(sm + OFF_W1 + n*PW1))[k] = __float2bfloat16(w1[k*128 + n]);
        ((__nv_bfloat16*)(sm + OFF_W2 + n*PW1))[k] = __float2bfloat16(w2[k*128 + n]);
    }
    for (int i = t; i < 128*192; i += 512) {          // w3t
        int n = i / 192, k = i % 192;
        ((__nv_bfloat16*)(sm + OFF_W3 + n*PW3))[k] =
            (k < 191) ? __float2bfloat16(w3[k*128 + n]) : __float2bfloat16(0.f);
    }
    if (t < 128) {
        float* bb = (float*)(sm + OFF_BIAS);
        bb[t] = b0[t]; bb[128 + t] = b1[t]; bb[256 + t] = b2[t]; bb[384 + t] = b3[t];
        float* wos = (float*)(sm + OFF_WO);
        wos[3*t+0] = wo[3*t+0]; wos[3*t+1] = wo[3*t+1]; wos[3*t+2] = wo[3*t+2];
    }
    if (t < 3) ((float*)(sm + OFF_BO))[t] = bo[t];
    __syncthreads();

    const uint32_t smb = [&]{ uint32_t a;
        asm("{ .reg .u64 t; cvta.to.shared.u64 t, %1; cvt.u32.u64 %0, t; }"
            : "=r"(a) : "l"(sm)); return a; }();

    const int lane = t & 31, warp = t >> 5;
    const int rg = warp >> 2, ch = warp & 3;   // group spread over SMSPs
    const int m0 = 32 * rg, ncol0 = 32 * ch;
    const int barid = rg + 1;
    const int r8 = lane >> 2, q = lane & 3;
    const int ntiles = (B + 31) >> 5;          // 32-point tiles
    const float* bias = (const float*)(sm + OFF_BIAS);
    const float* wos  = (const float*)(sm + OFF_WO);
    const float* bos  = (const float*)(sm + OFF_BO);

    // de-phase the 4 groups so pipe usage interleaves across groups
    __nanosleep(rg * 600);

    for (int tile = blockIdx.x * 4 + rg; tile < ntiles; tile += gridDim.x * 4) {
        int pbase = tile * 32;

        // ---- positional encoding: lanes 0..7, row = m0 + 8*ch + lane ----
        if (lane < 8) {
            int lr = 8*ch + lane;
            int p = pbase + lr;
            __nv_bfloat16* fr = (__nv_bfloat16*)(sm + OFF_BUFA + (m0 + lr) * PBA + 256);
            float xv0 = 0.f, xv1 = 0.f, xv2 = 0.f;
            if (p < B) { xv0 = x[3*p]; xv1 = x[3*p+1]; xv2 = x[3*p+2]; }
            fr[0] = __float2bfloat16(xv0);
            fr[1] = __float2bfloat16(xv1);
            fr[2] = __float2bfloat16(xv2);
            float s0 = sinf(xv0), c0v = cosf(xv0);
            float s1 = sinf(xv1), c1v = cosf(xv1);
            float s2 = sinf(xv2), c2v = cosf(xv2);
            #pragma unroll
            for (int b = 0; b < 10; b++) {
                int f = 3 + b*6;
                fr[f+0] = __float2bfloat16(s0);
                fr[f+1] = __float2bfloat16(s1);
                fr[f+2] = __float2bfloat16(s2);
                fr[f+3] = __float2bfloat16(c0v);
                fr[f+4] = __float2bfloat16(c1v);
                fr[f+5] = __float2bfloat16(c2v);
                float ns0 = 2.f*s0*c0v, nc0 = 2.f*c0v*c0v - 1.f;
                float ns1 = 2.f*s1*c1v, nc1 = 2.f*c1v*c1v - 1.f;
                float ns2 = 2.f*s2*c2v, nc2 = 2.f*c2v*c2v - 1.f;
                s0 = ns0; c0v = nc0; s1 = ns1; c1v = nc1; s2 = ns2; c2v = nc2;
            }
            fr[63] = __float2bfloat16(0.f);
        }
        asm volatile("bar.sync %0, 128;" :: "r"(barid) : "memory");

        float acc[2][4][4];

        // L0: feats(64) -> h0 (bufB)
        zero_acc(acc);
        gemm32x32(smb, OFF_BUFA + 256, PBA, OFF_W0, PW0, 4, acc, lane, m0, ncol0);
        epi32x32(sm, OFF_BUFB, PBB, bias + 0, acc, lane, m0, ncol0);
        asm volatile("bar.sync %0, 128;" :: "r"(barid) : "memory");

        // L1: h0 -> h1 (bufA cols 0..127)
        zero_acc(acc);
        gemm32x32(smb, OFF_BUFB, PBB, OFF_W1, PW1, 8, acc, lane, m0, ncol0);
        epi32x32(sm, OFF_BUFA, PBA, bias + 128, acc, lane, m0, ncol0);
        asm volatile("bar.sync %0, 128;" :: "r"(barid) : "memory");

        // L2: h1 -> h2 (bufB)
        zero_acc(acc);
        gemm32x32(smb, OFF_BUFA, PBA, OFF_W2, PW1, 8, acc, lane, m0, ncol0);
        epi32x32(sm, OFF_BUFB, PBB, bias + 256, acc, lane, m0, ncol0);
        asm volatile("bar.sync %0, 128;" :: "r"(barid) : "memory");

        // L3: concat[h2 (bufB, k0..127), feats (bufA cols 128.., k128..191)]
        //     + FUSED output projection (no h3 store)
        zero_acc(acc);
        gemm32x32(smb, OFF_BUFB, PBB, OFF_W3, PW3, 8, acc, lane, m0, ncol0);
        gemm32x32(smb, OFF_BUFA + 256, PBA, OFF_W3 + 256, PW3, 4, acc, lane, m0, ncol0);
        {
            const float* b3s = bias + 384;
            float s[4][3];
            #pragma unroll
            for (int i = 0; i < 4; i++) { s[i][0] = s[i][1] = s[i][2] = 0.f; }
            #pragma unroll
            for (int mt = 0; mt < 2; mt++) {
                #pragma unroll
                for (int nt = 0; nt < 4; nt++) {
                    int n = ncol0 + nt*8 + 2*q;
                    float b0v = b3s[n], b1v = b3s[n+1];
                    float v00 = fmaxf(acc[mt][nt][0] + b0v, 0.f);
                    float v01 = fmaxf(acc[mt][nt][1] + b1v, 0.f);
                    float v10 = fmaxf(acc[mt][nt][2] + b0v, 0.f);
                    float v11 = fmaxf(acc[mt][nt][3] + b1v, 0.f);
                    const float* wp = wos + 3*n;
                    float w00 = wp[0], w01 = wp[1], w02 = wp[2];
                    float w10 = wp[3], w11 = wp[4], w12 = wp[5];
                    s[2*mt+0][0] += v00*w00 + v01*w10;
                    s[2*mt+0][1] += v00*w01 + v01*w11;
                    s[2*mt+0][2] += v00*w02 + v01*w12;
                    s[2*mt+1][0] += v10*w00 + v11*w10;
                    s[2*mt+1][1] += v10*w01 + v11*w11;
                    s[2*mt+1][2] += v10*w02 + v11*w12;
                }
            }
            #pragma unroll
            for (int i = 0; i < 4; i++)
                #pragma unroll
                for (int j = 0; j < 3; j++) {
                    s[i][j] += __shfl_xor_sync(0xffffffff, s[i][j], 1);
                    s[i][j] += __shfl_xor_sync(0xffffffff, s[i][j], 2);
                }
            // stage partials in dead h1 region of bufA (cols 0..11 f32)
            if (q == 0) {
                #pragma unroll
                for (int i = 0; i < 4; i++) {
                    int row = m0 + 16*(i >> 1) + 8*(i & 1) + r8;
                    float* rp = (float*)(sm + OFF_BUFA + row * PBA) + ch*3;
                    rp[0] = s[i][0]; rp[1] = s[i][1]; rp[2] = s[i][2];
                }
            }
        }
        asm volatile("bar.sync %0, 128;" :: "r"(barid) : "memory");

        // ---- Rodrigues: lanes 0..7, row = m0 + 8*ch + lane ----
        if (lane < 8) {
            int lr = 8*ch + lane;
            int p = pbase + lr;
            if (p < B) {
                const float* rrow = (const float*)(sm + OFF_BUFA + (m0 + lr) * PBA);
                float r0 = bos[0], r1 = bos[1], r2 = bos[2];
                #pragma unroll
                for (int c = 0; c < 4; c++) {
                    r0 += rrow[c*3+0]; r1 += rrow[c*3+1]; r2 += rrow[c*3+2];
                }
                float theta = sqrtf(r0*r0 + r1*r1 + r2*r2 + 1e-12f);
                float it = 1.f / theta;
                float e0 = r0*it, e1 = r1*it, e2 = r2*it;
                float cd0 = out[B + 3*p], cd1 = out[B + 3*p+1], cd2 = out[B + 3*p+2];
                float a = sqrtf(cd0*cd0 + cd1*cd1 + cd2*cd2 + 1e-12f);
                float ia = 1.f / a;
                float v0 = cd0*ia, v1 = cd1*ia, v2 = cd2*ia;
                float ct = cosf(theta), st = sinf(theta);
                float cr0 = e1*v2 - e2*v1;
                float cr1 = e2*v0 - e0*v2;
                float cr2 = e0*v1 - e1*v0;
                float dt = e0*v0 + e1*v1 + e2*v2;
                float omc = (1.f - ct) * dt;
                out[4*B + 3*p+0] = a * (ct*v0 + st*cr0 + omc*e0);
                out[4*B + 3*p+1] = a * (ct*v1 + st*cr1 + omc*e1);
                out[4*B + 3*p+2] = a * (ct*v2 + st*cr2 + omc*e2);
            }
        }
        asm volatile("bar.sync %0, 128;" :: "r"(barid) : "memory");
    }
}

// ---------------------------------------------------------------------------
extern "C" void kernel_launch(void* const* d_in, const int* in_sizes, int n_in,
                              void* d_out, int out_size)
{
    const float* x    = (const float*)d_in[0];
    const float* grid = (const float*)d_in[1];
    const float* w0   = (const float*)d_in[2];
    const float* b0   = (const float*)d_in[3];
    const float* w1   = (const float*)d_in[4];
    const float* b1   = (const float*)d_in[5];
    const float* w2   = (const float*)d_in[6];
    const float* b2   = (const float*)d_in[7];
    const float* w3   = (const float*)d_in[8];
    const float* b3   = (const float*)d_in[9];
    const float* wo   = (const float*)d_in[10];
    const float* bo   = (const float*)d_in[11];
    float* out = (float*)d_out;
    int B = in_sizes[0] / 3;

    gather_kernel<<<(B + 255) / 256, 256>>>(x, grid, out, B);

    int nsm = 148;
    cudaDeviceGetAttribute(&nsm, cudaDevAttrMultiProcessorCount, 0);
    cudaFuncSetAttribute(mlp_kernel,
                         cudaFuncAttributeMaxDynamicSharedMemorySize, SMEM_BYTES);
    mlp_kernel<<<nsm, 512, SMEM_BYTES>>>(x, w0, b0, w1, b1, w2, b2,
                                         w3, b3, wo, bo, out, B);
}